// round 15
// baseline (speedup 1.0000x reference)
#include <cuda_runtime.h>

// left, right: [B, C, H, W] fp32 ; out: [B, C, D, H, W] fp32
#define BB 2
#define CC 32
#define HH 96
#define WW 320
#define DISP 48
#define W4 (WW / 4)              // 80 float4 per row
#define NGROUPS 12               // disparity groups
#define DG (DISP / NGROUPS)      // 4 disparities per group
#define NTHREADS (W4 * NGROUPS)  // 960

__global__ __launch_bounds__(NTHREADS)
void diffvolume_kernel(const float* __restrict__ left,
                       const float* __restrict__ right,
                       float* __restrict__ out) {
    // h-major block order: concurrent blocks span ALL bc chunks, spreading
    // the instantaneous write footprint across the whole 377MB output
    // (more DRAM bank-level parallelism in the drain). Work per block is
    // byte-identical to the 54.3us champion; only bid->(bc,h) decode changes.
    const int bc = blockIdx.x % (BB * CC);
    const int h  = blockIdx.x / (BB * CC);
    const int row = bc * HH + h;             // input row index (unchanged math)
    const int t = threadIdx.x;

    const int w4 = t % W4;                   // fixed output column (float4)
    const int dg = t / W4;                   // disparity group 0..11
    const int d0 = dg * DG;                  // multiple of 4 -> aligned window
    const int w0 = w4 * 4;

    const float* lrow = left  + (size_t)row * WW;
    const float* rrow = right + (size_t)row * WW;

    // Left operand: one coalesced float4 load, reused for all 4 disparities.
    const float4 lv = __ldg((const float4*)(lrow + w0));

    // Initial right window for d = d0. Out-of-range values are garbage, but
    // every consumer is masked by (w0+k >= d) == (src >= 0). Clamp keeps
    // 16B alignment (w0, d0 are multiples of 4).
    int i0 = w0 - d0;
    if (i0 < 0) i0 = 0;
    const float4 q = __ldg((const float4*)(rrow + i0));
    float r0 = q.x, r1 = q.y, r2 = q.z, r3 = q.w;

    // Prefetch the 3 sliding right-operand scalars up front (front-batched).
    float nr[DG - 1];
#pragma unroll
    for (int it = 0; it < DG - 1; ++it) {
        int si = w0 - (d0 + it) - 1;
        if (si < 0) si = 0;                  // clamped -> consumer is masked
        nr[it] = __ldg(rrow + si);           // coalesced 128B per warp
    }

    float4* out4 = (float4*)out;
    // out[bc, d, h, w4] = ((bc*DISP + d)*HH + h)*W4 + w4
    int oidx = ((bc * DISP + d0) * HH + h) * W4 + w4;

#pragma unroll
    for (int it = 0; it < DG; ++it) {
        const int d = d0 + it;
        float4 o;
        o.x = (w0 + 0 >= d) ? lv.x - r0 : 0.f;
        o.y = (w0 + 1 >= d) ? lv.y - r1 : 0.f;
        o.z = (w0 + 2 >= d) ? lv.z - r2 : 0.f;
        o.w = (w0 + 3 >= d) ? lv.w - r3 : 0.f;
        __stcs(&out4[oidx], o);              // evict-first streaming store:
        oidx += HH * W4;                     // proven load-bearing (R5/R7)

        if (it < DG - 1) {
            // slide: r(d+1) = { right[w0-d-1], r0, r1, r2 }
            r3 = r2; r2 = r1; r1 = r0; r0 = nr[it];
        }
    }
}

extern "C" void kernel_launch(void* const* d_in, const int* in_sizes, int n_in,
                              void* d_out, int out_size) {
    const float* left  = (const float*)d_in[0];
    const float* right = (const float*)d_in[1];
    float* out = (float*)d_out;

    dim3 grid(BB * CC * HH);   // 6144 blocks, h-major order
    diffvolume_kernel<<<grid, NTHREADS>>>(left, right, out);
}

// round 16
// speedup vs baseline: 1.0691x; 1.0691x over previous
#include <cuda_runtime.h>

// left, right: [B, C, H, W] fp32 ; out: [B, C, D, H, W] fp32
#define BB 2
#define CC 32
#define HH 96
#define WW 320
#define DISP 48
#define W4 (WW / 4)              // 80 float4 per row
#define NGROUPS 12               // disparity groups
#define DG (DISP / NGROUPS)      // 4 disparities per group
#define NTHREADS (W4 * NGROUPS)  // 960

__global__ __launch_bounds__(NTHREADS)
void diffvolume_kernel(const float* __restrict__ left,
                       const float* __restrict__ right,
                       float* __restrict__ out) {
    const int row = blockIdx.x;              // bc*HH + h  (bc-major: compact
    const int t = threadIdx.x;               // concurrent write footprint)

    const int w4 = t % W4;                   // fixed output column (float4)
    const int dg = t / W4;                   // disparity group 0..11
    const int d0 = dg * DG;                  // multiple of 4 -> aligned window
    const int w0 = w4 * 4;

    const float* lrow = left  + (size_t)row * WW;
    const float* rrow = right + (size_t)row * WW;

    // Left operand: one coalesced float4 load, reused for all 4 disparities.
    const float4 lv = __ldg((const float4*)(lrow + w0));

    // Initial right window for d = d0. Out-of-range values are garbage, but
    // every consumer is masked by (w0+k >= d) == (src >= 0). Clamp keeps
    // 16B alignment (w0, d0 are multiples of 4).
    int i0 = w0 - d0;
    if (i0 < 0) i0 = 0;
    const float4 q = __ldg((const float4*)(rrow + i0));
    float r0 = q.x, r1 = q.y, r2 = q.z, r3 = q.w;

    // Prefetch the 3 sliding right-operand scalars up front (front-batched).
    float nr[DG - 1];
#pragma unroll
    for (int it = 0; it < DG - 1; ++it) {
        int si = w0 - (d0 + it) - 1;
        if (si < 0) si = 0;                  // clamped -> consumer is masked
        nr[it] = __ldg(rrow + si);           // coalesced 128B per warp
    }

    const int bc = row / HH;
    const int h  = row - bc * HH;

    float4* out4 = (float4*)out;
    // out[bc, d, h, w4] = ((bc*DISP + d)*HH + h)*W4 + w4
    int oidx = ((bc * DISP + d0) * HH + h) * W4 + w4;

#pragma unroll
    for (int it = 0; it < DG; ++it) {
        const int d = d0 + it;
        float4 o;
        o.x = (w0 + 0 >= d) ? lv.x - r0 : 0.f;
        o.y = (w0 + 1 >= d) ? lv.y - r1 : 0.f;
        o.z = (w0 + 2 >= d) ? lv.z - r2 : 0.f;
        o.w = (w0 + 3 >= d) ? lv.w - r3 : 0.f;
        __stcs(&out4[oidx], o);              // evict-first streaming store:
        oidx += HH * W4;                     // proven load-bearing (R5/R7)

        if (it < DG - 1) {
            // slide: r(d+1) = { right[w0-d-1], r0, r1, r2 }
            r3 = r2; r2 = r1; r1 = r0; r0 = nr[it];
        }
    }
}

extern "C" void kernel_launch(void* const* d_in, const int* in_sizes, int n_in,
                              void* d_out, int out_size) {
    const float* left  = (const float*)d_in[0];
    const float* right = (const float*)d_in[1];
    float* out = (float*)d_out;

    dim3 grid(BB * CC * HH);   // 6144 blocks, one per (b, c, h) row pair
    diffvolume_kernel<<<grid, NTHREADS>>>(left, right, out);
}